// round 1
// baseline (speedup 1.0000x reference)
#include <cuda_runtime.h>

// ---------------- problem constants ----------------
#define NPTS 32768          // B*S = 8*4096
#define DD   512            // feature dim
#define KC   4096           // codes per codebook
#define LC   3              // layers
#define NQ   ((size_t)NPTS * DD)        // 16777216 quantized_sum elements
#define NIDX ((size_t)NPTS * LC)        // 98304 index elements

// ---------------- device scratch (static; no allocation) ----------------
__device__ float g_resid[NPTS * DD];            // 64 MB residual buffer
__device__ float g_c[LC * KC];                  // 0.5*||E_k||^2
__device__ unsigned long long g_best[NPTS];     // packed (score, ~col)
__device__ int g_counts[LC * KC];               // histogram per layer
__device__ double g_commit;                     // sum of residual^2 across layers
__device__ float g_perp[LC];                    // per-layer perplexity

// ---------------- init / zero kernels ----------------
__global__ void init_kernel() {
    int i = blockIdx.x * blockDim.x + threadIdx.x;
    if (i < NPTS) g_best[i] = 0ULL;
    if (i < LC * KC) g_counts[i] = 0;
    if (i == 0) g_commit = 0.0;
}

__global__ void zero_best_kernel() {
    int i = blockIdx.x * blockDim.x + threadIdx.x;
    if (i < NPTS) g_best[i] = 0ULL;
}

// ---------------- 0.5*||E||^2 per codebook row ----------------
__global__ void colnorm_kernel(const float* __restrict__ cb) {
    int warp = (blockIdx.x * blockDim.x + threadIdx.x) >> 5;
    int lane = threadIdx.x & 31;
    if (warp >= LC * KC) return;
    const float4* row = (const float4*)(cb + (size_t)warp * DD);
    float s = 0.f;
    #pragma unroll
    for (int i = lane; i < DD / 4; i += 32) {
        float4 v = row[i];
        s += v.x * v.x + v.y * v.y + v.z * v.z + v.w * v.w;
    }
    #pragma unroll
    for (int o = 16; o; o >>= 1) s += __shfl_down_sync(0xffffffffu, s, o);
    if (lane == 0) g_c[warp] = 0.5f * s;
}

// ---------------- fused GEMM (scores) + row argmax ----------------
// score[n][k] = resid[n] . E[k] - 0.5*||E[k]||^2 ; best per n via packed atomicMax.
// 128x128 tile, BK=16, 256 threads, 8x8 microtile.
__global__ __launch_bounds__(256) void gemm_argmax_kernel(
    const float* __restrict__ Ain, const float* __restrict__ cb,
    int layer, int use_resid)
{
    const float* A = use_resid ? g_resid : Ain;
    const float* E = cb + (size_t)layer * KC * DD;
    const float* c = g_c + layer * KC;

    __shared__ __align__(16) float As[16][132];
    __shared__ __align__(16) float Bs[16][132];

    int tid = threadIdx.x;
    int tx = tid & 15, ty = tid >> 4;
    int m0 = blockIdx.x * 128, n0 = blockIdx.y * 128;

    float acc[8][8] = {};

    for (int k0 = 0; k0 < DD; k0 += 16) {
        #pragma unroll
        for (int i = 0; i < 2; i++) {
            int f = tid + i * 256;          // 0..511
            int m = f >> 2;                 // 0..127
            int kq = (f & 3) << 2;          // 0,4,8,12
            float4 va = *(const float4*)(A + (size_t)(m0 + m) * DD + k0 + kq);
            As[kq + 0][m] = va.x; As[kq + 1][m] = va.y;
            As[kq + 2][m] = va.z; As[kq + 3][m] = va.w;
            float4 vb = *(const float4*)(E + (size_t)(n0 + m) * DD + k0 + kq);
            Bs[kq + 0][m] = vb.x; Bs[kq + 1][m] = vb.y;
            Bs[kq + 2][m] = vb.z; Bs[kq + 3][m] = vb.w;
        }
        __syncthreads();
        #pragma unroll
        for (int k = 0; k < 16; k++) {
            float a[8], b[8];
            *(float4*)&a[0] = *(const float4*)&As[k][ty * 8];
            *(float4*)&a[4] = *(const float4*)&As[k][ty * 8 + 4];
            *(float4*)&b[0] = *(const float4*)&Bs[k][tx * 8];
            *(float4*)&b[4] = *(const float4*)&Bs[k][tx * 8 + 4];
            #pragma unroll
            for (int i = 0; i < 8; i++)
                #pragma unroll
                for (int j = 0; j < 8; j++)
                    acc[i][j] = fmaf(a[i], b[j], acc[i][j]);
        }
        __syncthreads();
    }

    // epilogue: per-row argmax over this 128-col tile, then global atomicMax
    #pragma unroll
    for (int i = 0; i < 8; i++) {
        unsigned long long bp = 0ULL;
        #pragma unroll
        for (int j = 0; j < 8; j++) {
            int col = n0 + tx * 8 + j;
            float s = acc[i][j] - __ldg(&c[col]);
            unsigned u = __float_as_uint(s);
            u = (u & 0x80000000u) ? ~u : (u | 0x80000000u);  // order-preserving map
            unsigned long long p = ((unsigned long long)u << 32)
                                 | (unsigned long long)(0xFFFFFFFFu - (unsigned)col);
            bp = p > bp ? p : bp;
        }
        #pragma unroll
        for (int o = 8; o; o >>= 1) {
            unsigned long long q = __shfl_down_sync(0xffffffffu, bp, o, 16);
            bp = q > bp ? q : bp;
        }
        if (tx == 0) atomicMax(&g_best[m0 + ty * 8 + i], bp);
    }
}

// ---------------- gather + residual update + commit + histogram ----------------
template <bool LAST>
__global__ void assign_kernel(const float* __restrict__ cbL, const float* __restrict__ z,
                              float* __restrict__ out_q, float* __restrict__ out_idx,
                              int layer, int first)
{
    int n = blockIdx.x;
    int t = threadIdx.x;  // 128 threads, one float4 each (D=512)
    unsigned long long p = g_best[n];
    int idx = (int)(0xFFFFFFFFu - (unsigned)(p & 0xFFFFFFFFull));
    if (t == 0) {
        out_idx[(size_t)n * LC + layer] = (float)idx;
        atomicAdd(&g_counts[layer * KC + idx], 1);
    }
    const float4* e = (const float4*)(cbL + (size_t)idx * DD);
    const float4* rin = first ? (const float4*)(z + (size_t)n * DD)
                              : (const float4*)(g_resid + (size_t)n * DD);
    float4 rv = rin[t];
    float4 ev = e[t];
    float4 rn = make_float4(rv.x - ev.x, rv.y - ev.y, rv.z - ev.z, rv.w - ev.w);
    float s = rn.x * rn.x + rn.y * rn.y + rn.z * rn.z + rn.w * rn.w;
    if (LAST) {
        float4 zv = ((const float4*)(z + (size_t)n * DD))[t];
        ((float4*)(out_q + (size_t)n * DD))[t] =
            make_float4(zv.x - rn.x, zv.y - rn.y, zv.z - rn.z, zv.w - rn.w);
    } else {
        ((float4*)(g_resid + (size_t)n * DD))[t] = rn;
    }
    #pragma unroll
    for (int o = 16; o; o >>= 1) s += __shfl_down_sync(0xffffffffu, s, o);
    __shared__ float red[4];
    if ((t & 31) == 0) red[t >> 5] = s;
    __syncthreads();
    if (t == 0) atomicAdd(&g_commit, (double)(red[0] + red[1] + red[2] + red[3]));
}

// ---------------- perplexity + scalar finalize ----------------
__global__ void perp_kernel() {
    int l = blockIdx.x;
    int t = threadIdx.x;
    float local = 0.f;
    for (int k = t; k < KC; k += 256) {
        float p = (float)g_counts[l * KC + k] * (1.0f / (float)NPTS);
        local += p * logf(p + 1e-10f);
    }
    #pragma unroll
    for (int o = 16; o; o >>= 1) local += __shfl_down_sync(0xffffffffu, local, o);
    __shared__ float red[8];
    if ((t & 31) == 0) red[t >> 5] = local;
    __syncthreads();
    if (t == 0) {
        float s = 0.f;
        #pragma unroll
        for (int i = 0; i < 8; i++) s += red[i];
        g_perp[l] = expf(-s);
    }
}

__global__ void final_kernel(float* __restrict__ out_sc) {
    out_sc[0] = (float)(g_commit * (0.25 / (double)NQ));             // total_commit
    out_sc[1] = (g_perp[0] + g_perp[1] + g_perp[2]) * (1.0f / 3.0f); // avg_perplexity
}

// ---------------- launch ----------------
extern "C" void kernel_launch(void* const* d_in, const int* in_sizes, int n_in,
                              void* d_out, int out_size)
{
    const float* z  = (const float*)d_in[0];   // [8,4096,512] f32
    const float* cb = (const float*)d_in[1];   // [3,4096,512] f32
    float* out = (float*)d_out;
    float* out_q   = out;                      // 16777216 f32
    float* out_idx = out + NQ;                 // 98304 f32 (indices cast)
    float* out_sc  = out_idx + NIDX;           // commit, avg_perplexity

    init_kernel<<<160, 256>>>();
    colnorm_kernel<<<(LC * KC * 32 + 255) / 256, 256>>>(cb);

    dim3 gg(NPTS / 128, KC / 128);
    for (int l = 0; l < LC; l++) {
        if (l) zero_best_kernel<<<128, 256>>>();
        gemm_argmax_kernel<<<gg, 256>>>(z, cb, l, l > 0 ? 1 : 0);
        const float* cbL = cb + (size_t)l * KC * DD;
        if (l < LC - 1)
            assign_kernel<false><<<NPTS, 128>>>(cbL, z, out_q, out_idx, l, l == 0 ? 1 : 0);
        else
            assign_kernel<true><<<NPTS, 128>>>(cbL, z, out_q, out_idx, l, 0);
    }
    perp_kernel<<<LC, 256>>>();
    final_kernel<<<1, 1>>>(out_sc);
}